// round 1
// baseline (speedup 1.0000x reference)
#include <cuda_runtime.h>
#include <math_constants.h>

// Problem shape (fixed by the reference): x/bias/a/b : [4,128,128,256] f32, NHWC.
// Pool 2x2 stride 2 -> out tensors [4,64,64,256], plus two scalars l_out, u_out.
// d_out layout (flattened tuple): out_x | out_bias | out_a | out_b | l | u.
namespace {
constexpr int Bn = 4, Hh = 128, Ww = 128, Cc = 256, Hp = 64, Wp = 64;
constexpr int NOUT = Bn * Hp * Wp * Cc;   // 4,194,304 per output tensor
constexpr int N4   = NOUT / 4;            // vec4 outputs: 1,048,576
constexpr int C4   = Cc / 4;              // 64
constexpr int WC4  = Ww * C4;             // 8192 (one H row, in float4 units)
constexpr int SCAL = 4 * NOUT;            // scalar slots: SCAL (l), SCAL+1 (u)
}

__device__ __forceinline__ float getc(const float4& v, int k) {
    return k == 0 ? v.x : (k == 1 ? v.y : (k == 2 ? v.z : v.w));
}
__device__ __forceinline__ void setc(float4& v, int k, float f) {
    if (k == 0) v.x = f; else if (k == 1) v.y = f; else if (k == 2) v.z = f; else v.w = f;
}

// Exact float max/min atomics via sign-aware integer ordering.
__device__ __forceinline__ void atomicMaxF(float* addr, float v) {
    if (v >= 0.0f) atomicMax((int*)addr, __float_as_int(v));
    else           atomicMin((unsigned int*)addr, __float_as_uint(v));
}
__device__ __forceinline__ void atomicMinF(float* addr, float v) {
    if (v >= 0.0f) atomicMin((int*)addr, __float_as_int(v));
    else           atomicMax((unsigned int*)addr, __float_as_uint(v));
}

// Seed the scalar output slots with the input l/u so the atomic lattice
// converges to exactly max(l, l_t) / min(u, u_t).
__global__ void init_scalars_kernel(const float* __restrict__ l,
                                    const float* __restrict__ u,
                                    float* __restrict__ out) {
    out[SCAL]     = l[0];
    out[SCAL + 1] = u[0];
}

__global__ void __launch_bounds__(256, 8)
pool_kernel(const float4* __restrict__ x,
            const float4* __restrict__ bias,
            const float4* __restrict__ a,
            const float4* __restrict__ b,
            float* __restrict__ out) {
    float4* __restrict__ out4 = reinterpret_cast<float4*>(out);

    float lloc = -CUDART_INF_F;
    float uloc =  CUDART_INF_F;

    const int stride = gridDim.x * blockDim.x;
    for (int i = blockIdx.x * blockDim.x + threadIdx.x; i < N4; i += stride) {
        // i indexes vec4 outputs: (((bb*Hp + hp)*Wp + wp)*C4 + c4)
        int c4 = i & (C4 - 1);
        int t  = i >> 6;            // C4 == 64
        int wp = t & (Wp - 1);
        t >>= 6;                    // Wp == 64
        int hp = t & (Hp - 1);
        int bb = t >> 6;            // Hp == 64
        // Input base in vec4 units at (bb, 2*hp, 2*wp, 4*c4)
        int base = ((bb * Hh + 2 * hp) * Ww + 2 * wp) * C4 + c4;

        // Window entry order matches the reference patch order:
        // (dh,dw) = (0,0),(0,1),(1,0),(1,1)
        const float4 X0 = x[base],    X1 = x[base + C4],
                     X2 = x[base + WC4], X3 = x[base + WC4 + C4];
        const float4 I0 = bias[base], I1 = bias[base + C4],
                     I2 = bias[base + WC4], I3 = bias[base + WC4 + C4];
        const float4 A0 = a[base],    A1 = a[base + C4],
                     A2 = a[base + WC4], A3 = a[base + WC4 + C4];
        const float4 B0 = b[base],    B1 = b[base + C4],
                     B2 = b[base + WC4], B3 = b[base + WC4 + C4];

        float4 ox, obi, oa, ob;
        #pragma unroll
        for (int ln = 0; ln < 4; ln++) {
            const float xv0 = getc(X0, ln), xv1 = getc(X1, ln),
                        xv2 = getc(X2, ln), xv3 = getc(X3, ln);
            // First-max argmax (strict >) matches jnp.argmax tie-breaking.
            int   idx  = 0;
            float best = xv0;
            if (xv1 > best) { best = xv1; idx = 1; }
            if (xv2 > best) { best = xv2; idx = 2; }
            if (xv3 > best) { best = xv3; idx = 3; }

            const float bi0 = getc(I0, ln), bi1 = getc(I1, ln),
                        bi2 = getc(I2, ln), bi3 = getc(I3, ln);
            const float a0  = getc(A0, ln), a1  = getc(A1, ln),
                        a2  = getc(A2, ln), a3  = getc(A3, ln);
            const float bv0 = getc(B0, ln), bv1 = getc(B1, ln),
                        bv2 = getc(B2, ln), bv3 = getc(B3, ln);

            const float bis = idx == 0 ? bi0 : idx == 1 ? bi1 : idx == 2 ? bi2 : bi3;
            const float as_ = idx == 0 ? a0  : idx == 1 ? a1  : idx == 2 ? a2  : a3;
            const float bs_ = idx == 0 ? bv0 : idx == 1 ? bv1 : idx == 2 ? bv2 : bv3;

            setc(ox,  ln, best);
            setc(obi, ln, bis);
            setc(oa,  ln, as_);
            setc(ob,  ln, bs_);

            // nom_j = -( (a_j - a_s) + (bi_j - bi_s) ) = (a_s + bi_s) - a_j - bi_j
            const float s = as_ + bis;
            const float n0 = s - a0 - bi0, n1 = s - a1 - bi1,
                        n2 = s - a2 - bi2, n3 = s - a3 - bi3;
            const float d0 = bv0 - bs_, d1 = bv1 - bs_,
                        d2 = bv2 - bs_, d3 = bv3 - bs_;

            if (d0 > 0.0f) uloc = fminf(uloc, n0 / d0);
            else if (d0 < 0.0f) lloc = fmaxf(lloc, n0 / d0);
            if (d1 > 0.0f) uloc = fminf(uloc, n1 / d1);
            else if (d1 < 0.0f) lloc = fmaxf(lloc, n1 / d1);
            if (d2 > 0.0f) uloc = fminf(uloc, n2 / d2);
            else if (d2 < 0.0f) lloc = fmaxf(lloc, n2 / d2);
            if (d3 > 0.0f) uloc = fminf(uloc, n3 / d3);
            else if (d3 < 0.0f) lloc = fmaxf(lloc, n3 / d3);
        }

        out4[i]          = ox;
        out4[N4 + i]     = obi;
        out4[2 * N4 + i] = oa;
        out4[3 * N4 + i] = ob;
    }

    // Warp reduce
    #pragma unroll
    for (int off = 16; off; off >>= 1) {
        lloc = fmaxf(lloc, __shfl_xor_sync(0xffffffffu, lloc, off));
        uloc = fminf(uloc, __shfl_xor_sync(0xffffffffu, uloc, off));
    }
    // Block reduce
    __shared__ float sl[8], su[8];
    const int warp = threadIdx.x >> 5;
    const int lane = threadIdx.x & 31;
    if (lane == 0) { sl[warp] = lloc; su[warp] = uloc; }
    __syncthreads();
    if (threadIdx.x == 0) {
        float lb = sl[0], ub = su[0];
        #pragma unroll
        for (int w = 1; w < 8; w++) {
            lb = fmaxf(lb, sl[w]);
            ub = fminf(ub, su[w]);
        }
        if (lb != -CUDART_INF_F) atomicMaxF(out + SCAL, lb);
        if (ub !=  CUDART_INF_F) atomicMinF(out + SCAL + 1, ub);
    }
}

extern "C" void kernel_launch(void* const* d_in, const int* in_sizes, int n_in,
                              void* d_out, int out_size) {
    const float4* x  = (const float4*)d_in[0];
    const float4* bi = (const float4*)d_in[1];
    const float4* a  = (const float4*)d_in[2];
    const float4* b  = (const float4*)d_in[3];
    const float*  l  = (const float*)d_in[4];
    const float*  u  = (const float*)d_in[5];
    float* out = (float*)d_out;

    init_scalars_kernel<<<1, 1>>>(l, u, out);
    // 8 CTAs/SM x 148 SMs = full occupancy; grid-stride covers N4.
    pool_kernel<<<1184, 256>>>(x, bi, a, b, out);
}

// round 2
// speedup vs baseline: 1.4174x; 1.4174x over previous
#include <cuda_runtime.h>
#include <math_constants.h>

// x/bias/a/b : [4,128,128,256] f32 NHWC; 2x2/2 argmax-pool of x, gather from
// all 4 tensors at the argmax, plus global truncation-interval reduction.
// d_out: out_x | out_bias | out_a | out_b | l | u (flattened).
namespace {
constexpr int Hh = 128, Ww = 128, Cc = 256, Hp = 64, Wp = 64;
constexpr int NOUT = 4 * Hp * Wp * Cc;    // 4,194,304 per output tensor
constexpr int N4   = NOUT / 4;            // 1,048,576 vec4 outputs
constexpr int C4   = Cc / 4;              // 64
constexpr int WC4  = Ww * C4;             // 8192
constexpr int SCAL = 4 * NOUT;            // scalar slots: l, u
}

__device__ __forceinline__ float getc(const float4& v, int k) {
    return k == 0 ? v.x : (k == 1 ? v.y : (k == 2 ? v.z : v.w));
}
__device__ __forceinline__ void setc(float4& v, int k, float f) {
    if (k == 0) v.x = f; else if (k == 1) v.y = f; else if (k == 2) v.z = f; else v.w = f;
}
__device__ __forceinline__ float sel4(float v0, float v1, float v2, float v3, int k) {
    return k == 0 ? v0 : (k == 1 ? v1 : (k == 2 ? v2 : v3));
}

// Exact float max/min atomics via sign-aware integer ordering.
__device__ __forceinline__ void atomicMaxF(float* addr, float v) {
    if (v >= 0.0f) atomicMax((int*)addr, __float_as_int(v));
    else           atomicMin((unsigned int*)addr, __float_as_uint(v));
}
__device__ __forceinline__ void atomicMinF(float* addr, float v) {
    if (v >= 0.0f) atomicMin((int*)addr, __float_as_int(v));
    else           atomicMax((unsigned int*)addr, __float_as_uint(v));
}

__global__ void init_scalars_kernel(const float* __restrict__ l,
                                    const float* __restrict__ u,
                                    float* __restrict__ out) {
    out[SCAL]     = l[0];
    out[SCAL + 1] = u[0];
}

__global__ void __launch_bounds__(256, 4)
pool_kernel(const float4* __restrict__ x,
            const float4* __restrict__ bias,
            const float4* __restrict__ a,
            const float4* __restrict__ b,
            float* __restrict__ out) {
    float4* __restrict__ out4 = reinterpret_cast<float4*>(out);

    const int i = blockIdx.x * 256 + threadIdx.x;   // exactly N4 threads
    // i = (((bb*Hp + hp)*Wp + wp)*C4 + c4)
    int c4 = i & (C4 - 1);
    int t  = i >> 6;
    int wp = t & (Wp - 1);
    t >>= 6;
    int hp = t & (Hp - 1);
    int bb = t >> 6;
    const int base = ((bb * Hh + 2 * hp) * Ww + 2 * wp) * C4 + c4;
    // Window order matches reference patches: (0,0),(0,1),(1,0),(1,1)
    const int o1 = C4, o2 = WC4, o3 = WC4 + C4;

    // ---- Phase 1: x -> argmax + out_x ----
    const float4 X0 = x[base], X1 = x[base + o1], X2 = x[base + o2], X3 = x[base + o3];
    int idx[4];
    float4 ox;
    #pragma unroll
    for (int ln = 0; ln < 4; ln++) {
        float v0 = getc(X0, ln), v1 = getc(X1, ln), v2 = getc(X2, ln), v3 = getc(X3, ln);
        int k = 0; float best = v0;                       // first-max (strict >)
        if (v1 > best) { best = v1; k = 1; }
        if (v2 > best) { best = v2; k = 2; }
        if (v3 > best) { best = v3; k = 3; }
        idx[ln] = k;
        setc(ox, ln, best);
    }
    out4[i] = ox;

    // ---- Phase 2: bias -> out_bias + partial noms (bis - bi_j) ----
    const float4 I0 = bias[base], I1 = bias[base + o1], I2 = bias[base + o2], I3 = bias[base + o3];
    float nb[4][4];
    float4 obi;
    #pragma unroll
    for (int ln = 0; ln < 4; ln++) {
        float v0 = getc(I0, ln), v1 = getc(I1, ln), v2 = getc(I2, ln), v3 = getc(I3, ln);
        float s = sel4(v0, v1, v2, v3, idx[ln]);
        setc(obi, ln, s);
        nb[ln][0] = s - v0; nb[ln][1] = s - v1; nb[ln][2] = s - v2; nb[ln][3] = s - v3;
    }
    out4[N4 + i] = obi;

    // ---- Phase 3: a -> out_a + full noms (nb + (as - a_j)) ----
    const float4 A0 = a[base], A1 = a[base + o1], A2 = a[base + o2], A3 = a[base + o3];
    float4 oa;
    #pragma unroll
    for (int ln = 0; ln < 4; ln++) {
        float v0 = getc(A0, ln), v1 = getc(A1, ln), v2 = getc(A2, ln), v3 = getc(A3, ln);
        float s = sel4(v0, v1, v2, v3, idx[ln]);
        setc(oa, ln, s);
        nb[ln][0] += s - v0; nb[ln][1] += s - v1; nb[ln][2] += s - v2; nb[ln][3] += s - v3;
    }
    out4[2 * N4 + i] = oa;

    // ---- Phase 4: b -> out_b + interval candidates ----
    float lloc = -CUDART_INF_F;
    float uloc =  CUDART_INF_F;
    const float4 B0 = b[base], B1 = b[base + o1], B2 = b[base + o2], B3 = b[base + o3];
    float4 ob;
    #pragma unroll
    for (int ln = 0; ln < 4; ln++) {
        float v0 = getc(B0, ln), v1 = getc(B1, ln), v2 = getc(B2, ln), v3 = getc(B3, ln);
        float s = sel4(v0, v1, v2, v3, idx[ln]);
        setc(ob, ln, s);
        float d0 = v0 - s, d1 = v1 - s, d2 = v2 - s, d3 = v3 - s;
        if (d0 > 0.0f) uloc = fminf(uloc, nb[ln][0] / d0);
        else if (d0 < 0.0f) lloc = fmaxf(lloc, nb[ln][0] / d0);
        if (d1 > 0.0f) uloc = fminf(uloc, nb[ln][1] / d1);
        else if (d1 < 0.0f) lloc = fmaxf(lloc, nb[ln][1] / d1);
        if (d2 > 0.0f) uloc = fminf(uloc, nb[ln][2] / d2);
        else if (d2 < 0.0f) lloc = fmaxf(lloc, nb[ln][2] / d2);
        if (d3 > 0.0f) uloc = fminf(uloc, nb[ln][3] / d3);
        else if (d3 < 0.0f) lloc = fmaxf(lloc, nb[ln][3] / d3);
    }
    out4[3 * N4 + i] = ob;

    // ---- Reduction: warp shuffle -> block shared -> 2 global atomics ----
    #pragma unroll
    for (int off = 16; off; off >>= 1) {
        lloc = fmaxf(lloc, __shfl_xor_sync(0xffffffffu, lloc, off));
        uloc = fminf(uloc, __shfl_xor_sync(0xffffffffu, uloc, off));
    }
    __shared__ float sl[8], su[8];
    const int warp = threadIdx.x >> 5;
    const int lane = threadIdx.x & 31;
    if (lane == 0) { sl[warp] = lloc; su[warp] = uloc; }
    __syncthreads();
    if (threadIdx.x == 0) {
        float lb = sl[0], ub = su[0];
        #pragma unroll
        for (int w = 1; w < 8; w++) {
            lb = fmaxf(lb, sl[w]);
            ub = fminf(ub, su[w]);
        }
        if (lb != -CUDART_INF_F) atomicMaxF(out + SCAL, lb);
        if (ub !=  CUDART_INF_F) atomicMinF(out + SCAL + 1, ub);
    }
}

extern "C" void kernel_launch(void* const* d_in, const int* in_sizes, int n_in,
                              void* d_out, int out_size) {
    const float4* x  = (const float4*)d_in[0];
    const float4* bi = (const float4*)d_in[1];
    const float4* a  = (const float4*)d_in[2];
    const float4* b  = (const float4*)d_in[3];
    const float*  l  = (const float*)d_in[4];
    const float*  u  = (const float*)d_in[5];
    float* out = (float*)d_out;

    init_scalars_kernel<<<1, 1>>>(l, u, out);
    pool_kernel<<<N4 / 256, 256>>>(x, bi, a, b, out);   // 4096 blocks, 1 vec4/thread
}

// round 3
// speedup vs baseline: 1.5381x; 1.0852x over previous
#include <cuda_runtime.h>
#include <math_constants.h>

// x/bias/a/b : [4,128,128,256] f32 NHWC; 2x2/2 argmax-pool of x, gather from
// all 4 tensors at the argmax, plus global truncation-interval reduction.
// d_out: out_x | out_bias | out_a | out_b | l | u (flattened).
namespace {
constexpr int Hh = 128, Ww = 128, Cc = 256, Hp = 64, Wp = 64;
constexpr int NOUT = 4 * Hp * Wp * Cc;    // 4,194,304 per output tensor
constexpr int N2   = NOUT / 2;            // 2,097,152 vec2 outputs
constexpr int C2   = Cc / 2;              // 128 (float2 per channel dim)
constexpr int WC2  = Ww * C2;             // 16384
constexpr int SCAL = 4 * NOUT;            // scalar slots: l, u
}

__device__ __forceinline__ float getc(const float2& v, int k) { return k == 0 ? v.x : v.y; }
__device__ __forceinline__ void  setc(float2& v, int k, float f) { if (k == 0) v.x = f; else v.y = f; }
__device__ __forceinline__ float sel4(float v0, float v1, float v2, float v3, int k) {
    return k == 0 ? v0 : (k == 1 ? v1 : (k == 2 ? v2 : v3));
}

// Exact float max/min atomics via sign-aware integer ordering.
__device__ __forceinline__ void atomicMaxF(float* addr, float v) {
    if (v >= 0.0f) atomicMax((int*)addr, __float_as_int(v));
    else           atomicMin((unsigned int*)addr, __float_as_uint(v));
}
__device__ __forceinline__ void atomicMinF(float* addr, float v) {
    if (v >= 0.0f) atomicMin((int*)addr, __float_as_int(v));
    else           atomicMax((unsigned int*)addr, __float_as_uint(v));
}

__global__ void init_scalars_kernel(const float* __restrict__ l,
                                    const float* __restrict__ u,
                                    float* __restrict__ out) {
    out[SCAL]     = l[0];
    out[SCAL + 1] = u[0];
}

__global__ void __launch_bounds__(256, 6)
pool_kernel(const float2* __restrict__ x,
            const float2* __restrict__ bias,
            const float2* __restrict__ a,
            const float2* __restrict__ b,
            float* __restrict__ out) {
    float2* __restrict__ out2 = reinterpret_cast<float2*>(out);

    const int i = blockIdx.x * 256 + threadIdx.x;   // exactly N2 threads
    // i = (((bb*Hp + hp)*Wp + wp)*C2 + c2)
    int c2 = i & (C2 - 1);
    int t  = i >> 7;            // C2 == 128
    int wp = t & (Wp - 1);
    t >>= 6;
    int hp = t & (Hp - 1);
    int bb = t >> 6;
    const int base = ((bb * Hh + 2 * hp) * Ww + 2 * wp) * C2 + c2;
    // Window order matches reference patches: (0,0),(0,1),(1,0),(1,1)
    const int o1 = C2, o2 = WC2, o3 = WC2 + C2;

    // ---- Phase 1: x -> argmax + out_x ----
    const float2 X0 = x[base], X1 = x[base + o1], X2 = x[base + o2], X3 = x[base + o3];
    int idx[2];
    float2 ox;
    #pragma unroll
    for (int ln = 0; ln < 2; ln++) {
        float v0 = getc(X0, ln), v1 = getc(X1, ln), v2 = getc(X2, ln), v3 = getc(X3, ln);
        int k = 0; float best = v0;                       // first-max (strict >)
        if (v1 > best) { best = v1; k = 1; }
        if (v2 > best) { best = v2; k = 2; }
        if (v3 > best) { best = v3; k = 3; }
        idx[ln] = k;
        setc(ox, ln, best);
    }
    out2[i] = ox;

    // ---- Phase 2: bias -> out_bias + partial noms (bis - bi_j) ----
    const float2 I0 = bias[base], I1 = bias[base + o1], I2 = bias[base + o2], I3 = bias[base + o3];
    float nb[2][4];
    float2 obi;
    #pragma unroll
    for (int ln = 0; ln < 2; ln++) {
        float v0 = getc(I0, ln), v1 = getc(I1, ln), v2 = getc(I2, ln), v3 = getc(I3, ln);
        float s = sel4(v0, v1, v2, v3, idx[ln]);
        setc(obi, ln, s);
        nb[ln][0] = s - v0; nb[ln][1] = s - v1; nb[ln][2] = s - v2; nb[ln][3] = s - v3;
    }
    out2[N2 + i] = obi;

    // ---- Phase 3: a -> out_a + full noms (nb + (as - a_j)) ----
    const float2 A0 = a[base], A1 = a[base + o1], A2 = a[base + o2], A3 = a[base + o3];
    float2 oa;
    #pragma unroll
    for (int ln = 0; ln < 2; ln++) {
        float v0 = getc(A0, ln), v1 = getc(A1, ln), v2 = getc(A2, ln), v3 = getc(A3, ln);
        float s = sel4(v0, v1, v2, v3, idx[ln]);
        setc(oa, ln, s);
        nb[ln][0] += s - v0; nb[ln][1] += s - v1; nb[ln][2] += s - v2; nb[ln][3] += s - v3;
    }
    out2[2 * N2 + i] = oa;

    // ---- Phase 4: b -> out_b + interval candidates ----
    float lloc = -CUDART_INF_F;
    float uloc =  CUDART_INF_F;
    const float2 B0 = b[base], B1 = b[base + o1], B2 = b[base + o2], B3 = b[base + o3];
    float2 ob;
    #pragma unroll
    for (int ln = 0; ln < 2; ln++) {
        float v0 = getc(B0, ln), v1 = getc(B1, ln), v2 = getc(B2, ln), v3 = getc(B3, ln);
        float s = sel4(v0, v1, v2, v3, idx[ln]);
        setc(ob, ln, s);
        float d0 = v0 - s, d1 = v1 - s, d2 = v2 - s, d3 = v3 - s;
        if (d0 > 0.0f) uloc = fminf(uloc, nb[ln][0] / d0);
        else if (d0 < 0.0f) lloc = fmaxf(lloc, nb[ln][0] / d0);
        if (d1 > 0.0f) uloc = fminf(uloc, nb[ln][1] / d1);
        else if (d1 < 0.0f) lloc = fmaxf(lloc, nb[ln][1] / d1);
        if (d2 > 0.0f) uloc = fminf(uloc, nb[ln][2] / d2);
        else if (d2 < 0.0f) lloc = fmaxf(lloc, nb[ln][2] / d2);
        if (d3 > 0.0f) uloc = fminf(uloc, nb[ln][3] / d3);
        else if (d3 < 0.0f) lloc = fmaxf(lloc, nb[ln][3] / d3);
    }
    out2[3 * N2 + i] = ob;

    // ---- Reduction: warp shuffle -> block shared -> 2 global atomics ----
    #pragma unroll
    for (int off = 16; off; off >>= 1) {
        lloc = fmaxf(lloc, __shfl_xor_sync(0xffffffffu, lloc, off));
        uloc = fminf(uloc, __shfl_xor_sync(0xffffffffu, uloc, off));
    }
    __shared__ float sl[8], su[8];
    const int warp = threadIdx.x >> 5;
    const int lane = threadIdx.x & 31;
    if (lane == 0) { sl[warp] = lloc; su[warp] = uloc; }
    __syncthreads();
    if (threadIdx.x == 0) {
        float lb = sl[0], ub = su[0];
        #pragma unroll
        for (int w = 1; w < 8; w++) {
            lb = fmaxf(lb, sl[w]);
            ub = fminf(ub, su[w]);
        }
        if (lb != -CUDART_INF_F) atomicMaxF(out + SCAL, lb);
        if (ub !=  CUDART_INF_F) atomicMinF(out + SCAL + 1, ub);
    }
}

extern "C" void kernel_launch(void* const* d_in, const int* in_sizes, int n_in,
                              void* d_out, int out_size) {
    const float2* x  = (const float2*)d_in[0];
    const float2* bi = (const float2*)d_in[1];
    const float2* a  = (const float2*)d_in[2];
    const float2* b  = (const float2*)d_in[3];
    const float*  l  = (const float*)d_in[4];
    const float*  u  = (const float*)d_in[5];
    float* out = (float*)d_out;

    init_scalars_kernel<<<1, 1>>>(l, u, out);
    pool_kernel<<<N2 / 256, 256>>>(x, bi, a, b, out);   // 8192 blocks, 1 vec2/thread
}

// round 4
// speedup vs baseline: 1.8397x; 1.1961x over previous
#include <cuda_runtime.h>
#include <math_constants.h>

// x/bias/a/b : [4,128,128,256] f32 NHWC; 2x2/2 argmax-pool of x, gather from
// all 4 tensors at the argmax, plus global truncation-interval reduction.
// d_out: out_x | out_bias | out_a | out_b | l | u (flattened).
namespace {
constexpr int Hh = 128, Ww = 128, Cc = 256, Hp = 64, Wp = 64;
constexpr int NOUT = 4 * Hp * Wp * Cc;    // 4,194,304 per output tensor
constexpr int N2   = NOUT / 2;            // 2,097,152 vec2 outputs
constexpr int C2   = Cc / 2;              // 128 (float2 units along C)
constexpr int WC2  = Ww * C2;             // 16384
constexpr int SCAL = 4 * NOUT;            // scalar slots: l, u
}

__device__ __forceinline__ float getc(const float2& v, int k) { return k == 0 ? v.x : v.y; }
__device__ __forceinline__ void  setc(float2& v, int k, float f) { if (k == 0) v.x = f; else v.y = f; }
__device__ __forceinline__ float sel4(float v0, float v1, float v2, float v3, int k) {
    return k == 0 ? v0 : (k == 1 ? v1 : (k == 2 ? v2 : v3));
}

// Exact float max/min atomics via sign-aware integer ordering.
__device__ __forceinline__ void atomicMaxF(float* addr, float v) {
    if (v >= 0.0f) atomicMax((int*)addr, __float_as_int(v));
    else           atomicMin((unsigned int*)addr, __float_as_uint(v));
}
__device__ __forceinline__ void atomicMinF(float* addr, float v) {
    if (v >= 0.0f) atomicMin((int*)addr, __float_as_int(v));
    else           atomicMax((unsigned int*)addr, __float_as_uint(v));
}

__global__ void init_scalars_kernel(const float* __restrict__ l,
                                    const float* __restrict__ u,
                                    float* __restrict__ out) {
    out[SCAL]     = l[0];
    out[SCAL + 1] = u[0];
}

__global__ void __launch_bounds__(256, 7)
pool_kernel(const float2* __restrict__ x,
            const float2* __restrict__ bias,
            const float2* __restrict__ a,
            const float2* __restrict__ b,
            float* __restrict__ out) {
    float2* __restrict__ out2 = reinterpret_cast<float2*>(out);

    const int i = blockIdx.x * 256 + threadIdx.x;   // exactly N2 threads
    // i = (((bb*Hp + hp)*Wp + wp)*C2 + c2)
    int c2 = i & (C2 - 1);
    int t  = i >> 7;            // C2 == 128
    int wp = t & (Wp - 1);
    t >>= 6;
    int hp = t & (Hp - 1);
    int bb = t >> 6;
    const int base = ((bb * Hh + 2 * hp) * Ww + 2 * wp) * C2 + c2;
    // Window order matches reference patches: (0,0),(0,1),(1,0),(1,1)
    const int o1 = C2, o2 = WC2, o3 = WC2 + C2;

    // ---- Phase 1: x -> argmax + out_x ----
    const float2 X0 = __ldcs(x + base), X1 = __ldcs(x + base + o1),
                 X2 = __ldcs(x + base + o2), X3 = __ldcs(x + base + o3);
    int idx[2];
    float2 ox;
    #pragma unroll
    for (int ln = 0; ln < 2; ln++) {
        float v0 = getc(X0, ln), v1 = getc(X1, ln), v2 = getc(X2, ln), v3 = getc(X3, ln);
        int k = 0; float best = v0;                       // first-max (strict >)
        if (v1 > best) { best = v1; k = 1; }
        if (v2 > best) { best = v2; k = 2; }
        if (v3 > best) { best = v3; k = 3; }
        idx[ln] = k;
        setc(ox, ln, best);
    }
    __stcs(out2 + i, ox);

    // ---- Phase 2: bias -> out_bias + partial noms (bis - bi_j) ----
    const float2 I0 = __ldcs(bias + base), I1 = __ldcs(bias + base + o1),
                 I2 = __ldcs(bias + base + o2), I3 = __ldcs(bias + base + o3);
    float nb[2][4];
    float2 obi;
    #pragma unroll
    for (int ln = 0; ln < 2; ln++) {
        float v0 = getc(I0, ln), v1 = getc(I1, ln), v2 = getc(I2, ln), v3 = getc(I3, ln);
        float s = sel4(v0, v1, v2, v3, idx[ln]);
        setc(obi, ln, s);
        nb[ln][0] = s - v0; nb[ln][1] = s - v1; nb[ln][2] = s - v2; nb[ln][3] = s - v3;
    }
    __stcs(out2 + N2 + i, obi);

    // ---- Phase 3: a -> out_a + full noms (nb + (as - a_j)) ----
    const float2 A0 = __ldcs(a + base), A1 = __ldcs(a + base + o1),
                 A2 = __ldcs(a + base + o2), A3 = __ldcs(a + base + o3);
    float2 oa;
    #pragma unroll
    for (int ln = 0; ln < 2; ln++) {
        float v0 = getc(A0, ln), v1 = getc(A1, ln), v2 = getc(A2, ln), v3 = getc(A3, ln);
        float s = sel4(v0, v1, v2, v3, idx[ln]);
        setc(oa, ln, s);
        nb[ln][0] += s - v0; nb[ln][1] += s - v1; nb[ln][2] += s - v2; nb[ln][3] += s - v3;
    }
    __stcs(out2 + 2 * N2 + i, oa);

    // ---- Phase 4: b -> out_b + interval candidates (branchless) ----
    float lloc = -CUDART_INF_F;
    float uloc =  CUDART_INF_F;
    const float2 B0 = __ldcs(b + base), B1 = __ldcs(b + base + o1),
                 B2 = __ldcs(b + base + o2), B3 = __ldcs(b + base + o3);
    float2 ob;
    #pragma unroll
    for (int ln = 0; ln < 2; ln++) {
        float v0 = getc(B0, ln), v1 = getc(B1, ln), v2 = getc(B2, ln), v3 = getc(B3, ln);
        float s = sel4(v0, v1, v2, v3, idx[ln]);
        setc(ob, ln, s);
        float d[4] = { v0 - s, v1 - s, v2 - s, v3 - s };
        #pragma unroll
        for (int j = 0; j < 4; j++) {
            // j==idx: 0/0 -> NaN, but both guards are false, so never used.
            float q = __fdividef(nb[ln][j], d[j]);
            uloc = (d[j] > 0.0f) ? fminf(uloc, q) : uloc;
            lloc = (d[j] < 0.0f) ? fmaxf(lloc, q) : lloc;
        }
    }
    __stcs(out2 + 3 * N2 + i, ob);

    // ---- Reduction: warp shuffle -> block shared -> 2 global atomics ----
    #pragma unroll
    for (int off = 16; off; off >>= 1) {
        lloc = fmaxf(lloc, __shfl_xor_sync(0xffffffffu, lloc, off));
        uloc = fminf(uloc, __shfl_xor_sync(0xffffffffu, uloc, off));
    }
    __shared__ float sl[8], su[8];
    const int warp = threadIdx.x >> 5;
    const int lane = threadIdx.x & 31;
    if (lane == 0) { sl[warp] = lloc; su[warp] = uloc; }
    __syncthreads();
    if (threadIdx.x == 0) {
        float lb = sl[0], ub = su[0];
        #pragma unroll
        for (int w = 1; w < 8; w++) {
            lb = fmaxf(lb, sl[w]);
            ub = fminf(ub, su[w]);
        }
        if (lb != -CUDART_INF_F) atomicMaxF(out + SCAL, lb);
        if (ub !=  CUDART_INF_F) atomicMinF(out + SCAL + 1, ub);
    }
}

extern "C" void kernel_launch(void* const* d_in, const int* in_sizes, int n_in,
                              void* d_out, int out_size) {
    const float2* x  = (const float2*)d_in[0];
    const float2* bi = (const float2*)d_in[1];
    const float2* a  = (const float2*)d_in[2];
    const float2* b  = (const float2*)d_in[3];
    const float*  l  = (const float*)d_in[4];
    const float*  u  = (const float*)d_in[5];
    float* out = (float*)d_out;

    init_scalars_kernel<<<1, 1>>>(l, u, out);
    pool_kernel<<<N2 / 256, 256>>>(x, bi, a, b, out);   // 8192 blocks, 1 vec2/thread
}